// round 11
// baseline (speedup 1.0000x reference)
#include <cuda_runtime.h>
#include <cstdint>
#include <cstddef>

#define BB 32
#define SS 64
#define TT 64
#define HH 1024
#define VV 32000
#define G3H 3072
#define NBLK 128
#define KC 128

// ---------------- scratch (device globals; no allocation allowed) ----------------
__device__ float g_Uk[BB * SS * HH];
__device__ float g_X[TT * BB * HH];
__device__ float g_GiX[TT * BB * G3H];
__device__ float g_Hall[TT * BB * HH];
__device__ float g_Q[BB * HH];
__device__ float g_GH[BB * G3H];
__device__ float g_GI[BB * G3H];
__device__ float g_Ctx[BB * HH];
__device__ float g_Sc[BB * SS];
__device__ unsigned g_arrive;

// ---------------- helpers ----------------
typedef unsigned long long ull;
struct __align__(16) ULL2 { ull x, y; };

__device__ __forceinline__ ull pk2(float lo, float hi) {
    ull r; asm("mov.b64 %0, {%1, %2};" : "=l"(r) : "f"(lo), "f"(hi)); return r;
}
__device__ __forceinline__ void upk2(ull v, float& lo, float& hi) {
    asm("mov.b64 {%0, %1}, %2;" : "=f"(lo), "=f"(hi) : "l"(v));
}
__device__ __forceinline__ void ffma2(ull& c, ull a, ull b) {
    asm("fma.rn.f32x2 %0, %1, %2, %0;" : "+l"(c) : "l"(a), "l"(b));
}
__device__ __forceinline__ float tanh_ap(float x) {
    float y; asm("tanh.approx.f32 %0, %1;" : "=f"(y) : "f"(x)); return y;
}
__device__ __forceinline__ unsigned ld_acq(unsigned* p) {
    unsigned v;
    asm volatile("ld.acquire.gpu.global.u32 %0, [%1];" : "=r"(v) : "l"(p) : "memory");
    return v;
}
// arrival: release-ordered add (folds the fence; no separate MEMBAR.GPU)
__device__ __forceinline__ void red_rel_add(unsigned* p, unsigned v) {
    asm volatile("red.release.gpu.global.add.u32 [%0], %1;" :: "l"(p), "r"(v) : "memory");
}
// grid-wide barrier: monotonic counter; tight acquire-spin (no nanosleep)
__device__ __forceinline__ void gridbar(unsigned target) {
    __syncthreads();
    if (threadIdx.x == 0) {
        red_rel_add(&g_arrive, 1u);
        while (ld_acq(&g_arrive) < target) { }
    }
    __syncthreads();
}
__device__ __forceinline__ unsigned t32(float x) {   // round-to-nearest tf32
    unsigned r; asm("cvt.rna.tf32.f32 %0, %1;" : "=r"(r) : "f"(x)); return r;
}
__device__ __forceinline__ void mma8(float& c0, float& c1, float& c2, float& c3,
                                     unsigned a0, unsigned a1, unsigned a2, unsigned a3,
                                     unsigned b0, unsigned b1) {
    asm volatile(
        "mma.sync.aligned.m16n8k8.row.col.f32.tf32.tf32.f32 "
        "{%0,%1,%2,%3}, {%4,%5,%6,%7}, {%8,%9}, {%0,%1,%2,%3};"
        : "+f"(c0), "+f"(c1), "+f"(c2), "+f"(c3)
        : "r"(a0), "r"(a1), "r"(a2), "r"(a3), "r"(b0), "r"(b1));
}

// =================================================================================
// tf32 tensor-core GEMM: C[M,N] = A[M,1024] (lda) * W[N,1024] (ldw)^T + bias
// block 128x128, 256 thr = 8 warps (2m x 4n), warp 64x32, K-chunk 32.
// Fragment loads software-pipelined across kk (double-buffered in registers).
// mode 0: C row-major ld=N.  mode 1: logits remap row r=t*32+b -> C[b][t*VV + n].
// =================================================================================
__global__ __launch_bounds__(256)
void gemmTC(const float* __restrict__ A, int lda,
            const float* __restrict__ W, int ldw,
            const float* __restrict__ bias, float* __restrict__ C, int N, int mode)
{
    __shared__ unsigned As[128][36];
    __shared__ unsigned Ws[128][36];
    const int tid = threadIdx.x;
    const int m0 = blockIdx.x * 128;
    const int n0 = blockIdx.y * 128;
    const int wid = tid >> 5, lane = tid & 31;
    const int gid = lane >> 2, tig = lane & 3;
    const int wm = (wid >> 2) * 64;
    const int wn = (wid & 3) * 32;

    const int lrow = tid >> 1;
    const int lcb = (tid & 1) << 4;
    const float* Arow = A + (size_t)(m0 + lrow) * lda + lcb;
    const float* Wrow = W + (size_t)(n0 + lrow) * ldw + lcb;

    float acc[4][4][4];
#pragma unroll
    for (int i = 0; i < 4; i++)
#pragma unroll
        for (int j = 0; j < 4; j++)
#pragma unroll
            for (int e = 0; e < 4; e++) acc[i][j][e] = 0.f;

    float4 ra[4], rw[4];
#pragma unroll
    for (int j = 0; j < 4; j++) {
        ra[j] = *(const float4*)(Arow + j * 4);
        rw[j] = *(const float4*)(Wrow + j * 4);
    }

    unsigned af[2][4][4], bf[2][4][2];

    for (int ck = 0; ck < HH / 32; ck++) {
        __syncthreads();
#pragma unroll
        for (int j = 0; j < 4; j++) {
            As[lrow][lcb + j * 4 + 0] = t32(ra[j].x);
            As[lrow][lcb + j * 4 + 1] = t32(ra[j].y);
            As[lrow][lcb + j * 4 + 2] = t32(ra[j].z);
            As[lrow][lcb + j * 4 + 3] = t32(ra[j].w);
            Ws[lrow][lcb + j * 4 + 0] = t32(rw[j].x);
            Ws[lrow][lcb + j * 4 + 1] = t32(rw[j].y);
            Ws[lrow][lcb + j * 4 + 2] = t32(rw[j].z);
            Ws[lrow][lcb + j * 4 + 3] = t32(rw[j].w);
        }
        __syncthreads();
        if (ck + 1 < HH / 32) {
            int kt = (ck + 1) * 32;
#pragma unroll
            for (int j = 0; j < 4; j++) {
                ra[j] = *(const float4*)(Arow + kt + j * 4);
                rw[j] = *(const float4*)(Wrow + kt + j * 4);
            }
        }
        // preload fragments for kk=0
#pragma unroll
        for (int mf = 0; mf < 4; mf++) {
            int r = wm + mf * 16 + gid;
            af[0][mf][0] = As[r][tig];
            af[0][mf][1] = As[r + 8][tig];
            af[0][mf][2] = As[r][tig + 4];
            af[0][mf][3] = As[r + 8][tig + 4];
        }
#pragma unroll
        for (int nf = 0; nf < 4; nf++) {
            int c = wn + nf * 8 + gid;
            bf[0][nf][0] = Ws[c][tig];
            bf[0][nf][1] = Ws[c][tig + 4];
        }
#pragma unroll
        for (int ks = 0; ks < 4; ks++) {
            const int cur = ks & 1, nxt = cur ^ 1;
            if (ks < 3) {
                const int kk = (ks + 1) * 8;
#pragma unroll
                for (int mf = 0; mf < 4; mf++) {
                    int r = wm + mf * 16 + gid;
                    af[nxt][mf][0] = As[r][kk + tig];
                    af[nxt][mf][1] = As[r + 8][kk + tig];
                    af[nxt][mf][2] = As[r][kk + tig + 4];
                    af[nxt][mf][3] = As[r + 8][kk + tig + 4];
                }
#pragma unroll
                for (int nf = 0; nf < 4; nf++) {
                    int c = wn + nf * 8 + gid;
                    bf[nxt][nf][0] = Ws[c][kk + tig];
                    bf[nxt][nf][1] = Ws[c][kk + tig + 4];
                }
            }
#pragma unroll
            for (int mf = 0; mf < 4; mf++)
#pragma unroll
                for (int nf = 0; nf < 4; nf++)
                    mma8(acc[mf][nf][0], acc[mf][nf][1], acc[mf][nf][2], acc[mf][nf][3],
                         af[cur][mf][0], af[cur][mf][1], af[cur][mf][2], af[cur][mf][3],
                         bf[cur][nf][0], bf[cur][nf][1]);
        }
    }

    // epilogue: bias add + (optional) logits row remap
#pragma unroll
    for (int mf = 0; mf < 4; mf++) {
#pragma unroll
        for (int rr = 0; rr < 2; rr++) {
            int m = m0 + wm + mf * 16 + gid + rr * 8;
            float* crow;
            if (mode == 1) {
                int tt = m >> 5, b = m & 31;
                crow = C + (size_t)b * ((size_t)TT * VV) + (size_t)tt * VV;
            } else {
                crow = C + (size_t)m * N;
            }
#pragma unroll
            for (int nf = 0; nf < 4; nf++) {
                int n = n0 + wn + nf * 8 + tig * 2;
                float2 v;
                v.x = acc[mf][nf][rr * 2 + 0] + bias[n];
                v.y = acc[mf][nf][rr * 2 + 1] + bias[n + 1];
                *(float2*)(crow + n) = v;
            }
        }
    }
}

// ---------------- per-step tile GEMM: C[32 x 32cols] = A[32,1024] @ W^T ----------
__device__ __forceinline__ void tile32(
    float (*As)[132], float (*Ws)[132],
    const float* __restrict__ A, int lda,
    const float* __restrict__ W, int ldw, int n0,
    const float* __restrict__ bias,
    const float* __restrict__ init, int ldi,
    float* __restrict__ C, int ldc, int tid)
{
    const int ml = tid >> 3;
    const int cl = tid & 7;
    const int kb = cl * 4;
    ull acc[4] = {0ull, 0ull, 0ull, 0ull};
    float4 ra[4], rw[4];
    const float* Arow = A + (size_t)ml * lda;
    const float* Wrow = W + (size_t)(n0 + ml) * ldw;

#pragma unroll
    for (int j = 0; j < 4; j++) {
        ra[j] = *(const float4*)(Arow + kb + j * 32);
        rw[j] = *(const float4*)(Wrow + kb + j * 32);
    }
    for (int ck = 0; ck < HH / KC; ck++) {
        __syncthreads();
#pragma unroll
        for (int j = 0; j < 4; j++) {
            *(float4*)&As[ml][kb + j * 32] = ra[j];
            *(float4*)&Ws[ml][kb + j * 32] = rw[j];
        }
        __syncthreads();
        if (ck + 1 < HH / KC) {
            int kc = (ck + 1) * KC;
#pragma unroll
            for (int j = 0; j < 4; j++) {
                ra[j] = *(const float4*)(Arow + kc + kb + j * 32);
                rw[j] = *(const float4*)(Wrow + kc + kb + j * 32);
            }
        }
#pragma unroll 16
        for (int k = 0; k < KC; k += 4) {
            ULL2 a = *(const ULL2*)&As[ml][k];
#pragma unroll
            for (int j = 0; j < 4; j++) {
                ULL2 w = *(const ULL2*)&Ws[cl + j * 8][k];
                ffma2(acc[j], a.x, w.x);
                ffma2(acc[j], a.y, w.y);
            }
        }
    }
#pragma unroll
    for (int j = 0; j < 4; j++) {
        float lo, hi;
        upk2(acc[j], lo, hi);
        int n = n0 + cl + j * 8;
        float v = lo + hi;
        if (bias) v += bias[n];
        if (init) v += init[(size_t)ml * ldi + n];
        C[(size_t)ml * ldc + n] = v;
    }
}

// ---------------- persistent recurrence: all 64 steps in one kernel --------------
__global__ __launch_bounds__(256, 1)
void recur(const float* __restrict__ h0, const float* __restrict__ enc,
           const float* __restrict__ Wa_w, const float* __restrict__ Wa_b,
           const float* __restrict__ W_hh, const float* __restrict__ b_hh,
           const float* __restrict__ W_ih,
           const float* __restrict__ Va_w, const float* __restrict__ Va_b,
           float* __restrict__ attn_out, float* __restrict__ hT_out)
{
    __shared__ float As[32][132];
    __shared__ float Ws[32][132];
    __shared__ float smq[HH];
    __shared__ float smva[HH];
    __shared__ float smsc[SS];
    __shared__ float smex[SS];

    const int blk = blockIdx.x;
    const int tid = threadIdx.x;
    unsigned bt = 0;

    for (int t = 0; t < TT; t++) {
        const float* hid = (t == 0) ? h0 : (g_Hall + (size_t)(t - 1) * BB * HH);

        // phase A: q (tasks 0..31) + GH (tasks 32..127)
        if (blk < 32)
            tile32(As, Ws, hid, HH, Wa_w, HH, blk * 32, Wa_b,
                   nullptr, 0, g_Q, HH, tid);
        else
            tile32(As, Ws, hid, HH, W_hh, HH, (blk - 32) * 32, b_hh,
                   nullptr, 0, g_GH, G3H, tid);
        bt += NBLK; gridbar(bt);

        // phase B1: scores[b][s] = Va . tanh(q[b] + Uk[b,s]) + Va_b
        {
            const int b = blk >> 2, sg = (blk & 3) * 16;
            for (int i = tid; i < HH; i += 256) {
                smq[i] = g_Q[b * HH + i];
                smva[i] = Va_w[i];
            }
            __syncthreads();
            const int w = tid >> 5, lane = tid & 31;
#pragma unroll
            for (int si = 0; si < 2; si++) {
                int s = sg + w * 2 + si;
                const float* uk = g_Uk + (size_t)(b * SS + s) * HH;
                float sum = 0.f;
#pragma unroll 8
                for (int h = lane; h < HH; h += 32)
                    sum += smva[h] * tanh_ap(smq[h] + uk[h]);
#pragma unroll
                for (int o = 16; o; o >>= 1)
                    sum += __shfl_xor_sync(0xffffffffu, sum, o);
                if (lane == 0) g_Sc[b * SS + s] = sum + Va_b[0];
            }
        }
        bt += NBLK; gridbar(bt);

        // phase B2: softmax + attentions output + context (h-quartered)
        {
            const int b = blk >> 2, hq = blk & 3;
            if (tid < SS) smsc[tid] = g_Sc[b * SS + tid];
            __syncthreads();
            float mx = -1e30f;
#pragma unroll
            for (int s = 0; s < SS; s++) mx = fmaxf(mx, smsc[s]);
            if (tid < SS) smex[tid] = expf(smsc[tid] - mx);
            __syncthreads();
            float sum = 0.f;
#pragma unroll
            for (int s = 0; s < SS; s++) sum += smex[s];
            const float inv = 1.f / sum;
            const int h = hq * 256 + tid;
            const float* eb = enc + (size_t)b * SS * HH + h;
            float acc = 0.f;
#pragma unroll 8
            for (int s = 0; s < SS; s++) acc += smex[s] * eb[(size_t)s * HH];
            g_Ctx[b * HH + h] = acc * inv;
            if (hq == 0 && tid < SS)
                attn_out[(size_t)b * TT * SS + (size_t)t * SS + tid] = smex[tid] * inv;
        }
        bt += NBLK; gridbar(bt);

        // phase C: GI = GiX[t] + ctx @ W_ih[:, H:]^T   (96 tile tasks)
        if (blk < 96) {
            tile32(As, Ws, g_Ctx, HH, W_ih + HH, 2 * HH, blk * 32, nullptr,
                   g_GiX + (size_t)t * BB * G3H, G3H, g_GI, G3H, tid);
        }
        bt += NBLK; gridbar(bt);

        // phase D: GRU combine (PyTorch semantics)
        if (blk < 32) {
            const int b = blk;
            for (int h = tid; h < HH; h += 256) {
                float ir = g_GI[b * G3H + h],           hr = g_GH[b * G3H + h];
                float iz = g_GI[b * G3H + HH + h],      hz = g_GH[b * G3H + HH + h];
                float in_ = g_GI[b * G3H + 2 * HH + h], hn = g_GH[b * G3H + 2 * HH + h];
                float r = 1.f / (1.f + expf(-(ir + hr)));
                float z = 1.f / (1.f + expf(-(iz + hz)));
                float nv = tanhf(in_ + r * hn);
                float hnew = (1.f - z) * nv + z * hid[b * HH + h];
                g_Hall[(size_t)t * BB * HH + b * HH + h] = hnew;
                if (t == TT - 1) hT_out[b * HH + h] = hnew;
            }
        }
        bt += NBLK; gridbar(bt);
    }
}

// tokens: tok(b,0)=SOS=1, tok(b,t)=target[b,t-1]; gather emb rows; reset barrier
__global__ __launch_bounds__(256)
void gather_emb(const int* __restrict__ target, const float* __restrict__ emb)
{
    if (blockIdx.x == 0 && threadIdx.x == 0) g_arrive = 0;  // stream-ordered reset
    const int r = blockIdx.x;            // r = t*32 + b
    const int t = r >> 5, b = r & 31;
    const int tok = (t == 0) ? 1 : target[b * TT + (t - 1)];
    const float4* src = (const float4*)(emb + (size_t)tok * HH);
    float4* dst = (float4*)(g_X + (size_t)r * HH);
    dst[threadIdx.x] = src[threadIdx.x];
}

extern "C" void kernel_launch(void* const* d_in, const int* in_sizes, int n_in,
                              void* d_out, int out_size)
{
    (void)in_sizes; (void)n_in; (void)out_size;
    const float* enc   = (const float*)d_in[0];
    const float* h0    = (const float*)d_in[1];
    const int*   tgt   = (const int*)d_in[2];
    const float* emb   = (const float*)d_in[3];
    const float* Wa_w  = (const float*)d_in[4];
    const float* Wa_b  = (const float*)d_in[5];
    const float* Ua_w  = (const float*)d_in[6];
    const float* Ua_b  = (const float*)d_in[7];
    const float* Va_w  = (const float*)d_in[8];
    const float* Va_b  = (const float*)d_in[9];
    const float* W_ih  = (const float*)d_in[10];
    const float* W_hh  = (const float*)d_in[11];
    const float* b_ih  = (const float*)d_in[12];
    const float* b_hh  = (const float*)d_in[13];
    const float* out_w = (const float*)d_in[14];
    const float* out_b = (const float*)d_in[15];

    float* out = (float*)d_out;
    float* dec_out  = out;                                          // B*T*V
    float* hT_out   = out + (size_t)BB * TT * VV;                   // B*H
    float* attn_out = out + (size_t)BB * TT * VV + (size_t)BB * HH; // B*T*S

    float *Uk, *X, *GiX, *Hall;
    cudaGetSymbolAddress((void**)&Uk, g_Uk);
    cudaGetSymbolAddress((void**)&X, g_X);
    cudaGetSymbolAddress((void**)&GiX, g_GiX);
    cudaGetSymbolAddress((void**)&Hall, g_Hall);

    // Phase 0: loop-invariant precomputation (also resets grid-barrier counter)
    gather_emb<<<TT * BB, 256>>>(tgt, emb);
    // Uk = enc @ Ua^T + Ua_b          [2048 x 1024], K=1024
    gemmTC<<<dim3((BB * SS) / 128, HH / 128), 256>>>(enc, HH, Ua_w, HH, Ua_b, Uk, HH, 0);
    // GiX = X @ W_ih[:, :H]^T + b_ih  [2048 x 3072], K=1024 (ldw = 2H)
    gemmTC<<<dim3((TT * BB) / 128, G3H / 128), 256>>>(X, HH, W_ih, 2 * HH, b_ih, GiX, G3H, 0);

    // Phase 1: persistent fused recurrence (all 64 steps, grid-barrier phased)
    recur<<<NBLK, 256>>>(h0, enc, Wa_w, Wa_b, W_hh, b_hh, W_ih, Va_w, Va_b,
                         attn_out, hT_out);

    // Phase 2: one batched vocab projection for all 64 steps (tensor cores, tf32)
    gemmTC<<<dim3((TT * BB) / 128, VV / 128), 256>>>(Hall, HH, out_w, HH, out_b,
                                                     dec_out, VV, 1);
}